// round 16
// baseline (speedup 1.0000x reference)
#include <cuda_runtime.h>
#include <cuda_bf16.h>
#include <mma.h>
#include <cstdint>

using namespace nvcuda;

// ---------------- constants ----------------
static constexpr int GX = 100, GY = 100, GZ = 20;
static constexpr int NVOX = GX * GY * GZ;            // 200000
static constexpr int MAXV = 60000, MAXP = 10;
static constexpr int N1 = 10 * 50 * 50;              // 25000
static constexpr int N2 = 5 * 25 * 25;               // 3125
static constexpr int P2D = 625;                      // 25*25
static constexpr int K1D = 11520;                    // 9*1280
static constexpr int K2D = 4608;                     // 9*512

// ---------------- device scratch ----------------
__device__ int           g_count[NVOX];
__device__ float         g_pbuf[(size_t)NVOX * MAXP * 5];
__device__ unsigned char g_m0[NVOX];
__device__ unsigned char g_m1[N1];
__device__ unsigned char g_m2[N2];
__device__ int           g_list0[MAXV];
__device__ int           g_list0cell[MAXV];
__device__ int           g_list1[N1];
__device__ int           g_list2[N2];
__device__ int           g_cntArr[3];

__device__ __align__(16) __nv_bfloat16 g_f0h[(size_t)NVOX * 128];
__device__ __align__(16) __nv_bfloat16 g_f0l[(size_t)NVOX * 128];
__device__ __align__(16) __nv_bfloat16 g_f1h[(size_t)NVOX * 64];
__device__ __align__(16) __nv_bfloat16 g_f1l[(size_t)NVOX * 64];
__device__ __align__(16) __nv_bfloat16 g_f2h[(size_t)N1 * 128];
__device__ __align__(16) __nv_bfloat16 g_f2l[(size_t)N1 * 128];
__device__ __align__(16) __nv_bfloat16 g_f3h[(size_t)N1 * 128];
__device__ __align__(16) __nv_bfloat16 g_f3l[(size_t)N1 * 128];
__device__ float g_feat4[(size_t)N2 * 256];
__device__ __align__(16) __nv_bfloat16 g_col1h[(size_t)P2D * K1D];
__device__ __align__(16) __nv_bfloat16 g_col1l[(size_t)P2D * K1D];
__device__ __align__(16) __nv_bfloat16 g_col2h[(size_t)P2D * K2D];
__device__ __align__(16) __nv_bfloat16 g_col2l[(size_t)P2D * K2D];
__device__ __align__(16) __nv_bfloat16 g_bev1h[(size_t)512 * P2D];
__device__ __align__(16) __nv_bfloat16 g_bev1l[(size_t)512 * P2D];
__device__ float g_part[(size_t)4 * 512 * P2D];

__device__ float g_vfe1t[5 * 32], g_vfe1b[32];
__device__ float g_vfe2t[32 * 128], g_vfe2b[128];
__device__ float g_bb1[512], g_bb2[256];
// bf16 split conv weights, [k][ic][oc] row-major
__device__ __align__(16) __nv_bfloat16 g_w1bfh[27 * 128 * 64];
__device__ __align__(16) __nv_bfloat16 g_w1bfl[27 * 128 * 64];
__device__ __align__(16) __nv_bfloat16 g_w2bfh[27 * 64 * 128];
__device__ __align__(16) __nv_bfloat16 g_w2bfl[27 * 64 * 128];
__device__ __align__(16) __nv_bfloat16 g_w3bfh[27 * 128 * 128];
__device__ __align__(16) __nv_bfloat16 g_w3bfl[27 * 128 * 128];
__device__ __align__(16) __nv_bfloat16 g_w4bfh[27 * 128 * 256];
__device__ __align__(16) __nv_bfloat16 g_w4bfl[27 * 128 * 256];
// bf16 split BEV weights, [r][oc] row-major
__device__ __align__(16) __nv_bfloat16 g_wb1h[(size_t)K1D * 512];
__device__ __align__(16) __nv_bfloat16 g_wb1l[(size_t)K1D * 512];
__device__ __align__(16) __nv_bfloat16 g_wb2h[(size_t)K2D * 256];
__device__ __align__(16) __nv_bfloat16 g_wb2l[(size_t)K2D * 256];

// ---------------- cp.async helpers ----------------
__device__ __forceinline__ uint32_t s2u(const void* p) {
    uint32_t a;
    asm("{ .reg .u64 t; cvta.to.shared.u64 t, %1; cvt.u32.u64 %0, t; }" : "=r"(a) : "l"(p));
    return a;
}
__device__ __forceinline__ void cpa16(uint32_t saddr, const void* g, unsigned srcsize) {
    asm volatile("cp.async.cg.shared.global [%0], [%1], 16, %2;"
                 :: "r"(saddr), "l"(g), "r"(srcsize));
}
__device__ __forceinline__ void cpa16f(uint32_t saddr, const void* g) {
    asm volatile("cp.async.cg.shared.global [%0], [%1], 16;"
                 :: "r"(saddr), "l"(g));
}
__device__ __forceinline__ void cpa_wait() {
    asm volatile("cp.async.commit_group;\ncp.async.wait_group 0;" ::: "memory");
}

// ---------------- fused scatter + weight prep ----------------
static constexpr int SCAT_BLOCKS = (250000 + 255) / 256;
// coalesced-read split: idx enumerates src linearly [oc][ic][k]
__device__ __forceinline__ void bf_one(const float* __restrict__ src, const float* __restrict__ g,
                                       __nv_bfloat16* __restrict__ dh, __nv_bfloat16* __restrict__ dl,
                                       int idx, int I, int O, int KK) {
    int k = idx % KK;
    int rest = idx / KK;
    int ic = rest % I;
    int oc = rest / I;
    float w = src[idx] * g[oc];
    __nv_bfloat16 h = __float2bfloat16(w);
    size_t di = ((size_t)k * I + ic) * O + oc;
    dh[di] = h;
    dl[di] = __float2bfloat16(w - __bfloat162float(h));
}

static constexpr int NB1 = 27 * 128 * 64, NB2 = 27 * 64 * 128, NB3 = 27 * 128 * 128, NB4 = 27 * 128 * 256;
static constexpr int NW1 = K1D * 512, NW2 = K2D * 256;
static constexpr int PREP_TOTAL = NW1 + NW2 + 512 + 256 + 160 + 32 + 4096 + 128
                                + NB1 + NB2 + NB3 + NB4;
static constexpr int PREP_BLOCKS = (PREP_TOTAL + 255) / 256;

__global__ void __launch_bounds__(256) scatter_prep(
    const float* __restrict__ pts, int N,
    const float* __restrict__ sp1_w, const float* __restrict__ sp1_g,
    const float* __restrict__ sp2_w, const float* __restrict__ sp2_g,
    const float* __restrict__ sp3_w, const float* __restrict__ sp3_g,
    const float* __restrict__ sp4_w, const float* __restrict__ sp4_g,
    const float* __restrict__ bev1_w, const float* __restrict__ bev1_g,
    const float* __restrict__ bev2_w, const float* __restrict__ bev2_g,
    const float* __restrict__ bev1_b, const float* __restrict__ bev1_be,
    const float* __restrict__ bev2_b, const float* __restrict__ bev2_be,
    const float* __restrict__ v1w, const float* __restrict__ v1b,
    const float* __restrict__ v1g, const float* __restrict__ v1be,
    const float* __restrict__ v2w, const float* __restrict__ v2b,
    const float* __restrict__ v2g, const float* __restrict__ v2be)
{
    if (blockIdx.x < SCAT_BLOCKS) {
        int i = blockIdx.x * 256 + threadIdx.x;
        if (i >= N) return;
        const float* p = pts + (size_t)i * 5;
        float x = p[0], y = p[1], z = p[2];
        if (x == 0.0f) return;
        int ix = (int)floorf(__fdiv_rn(__fsub_rn(x, -51.2f), 1.024f));
        int iy = (int)floorf(__fdiv_rn(__fsub_rn(y, -51.2f), 1.024f));
        int iz = (int)floorf(__fdiv_rn(__fsub_rn(z, -5.0f), 0.4f));
        if (ix < 0 || ix >= GX || iy < 0 || iy >= GY || iz < 0 || iz >= GZ) return;
        int h = ix * (GY * GZ) + iy * GZ + iz;
        int r = atomicAdd(&g_count[h], 1);
        if (r < MAXP) {
            float* d = g_pbuf + ((size_t)h * MAXP + r) * 5;
            d[0] = x; d[1] = y; d[2] = z; d[3] = p[3]; d[4] = p[4];
        }
        return;
    }
    int idx = (blockIdx.x - SCAT_BLOCKS) * 256 + threadIdx.x;
    if (idx < NW1) { bf_one(bev1_w, bev1_g, g_wb1h, g_wb1l, idx, 1280, 512, 9); return; } idx -= NW1;
    if (idx < NW2) { bf_one(bev2_w, bev2_g, g_wb2h, g_wb2l, idx, 512, 256, 9); return; } idx -= NW2;
    if (idx < 512) { g_bb1[idx] = bev1_b[idx] * bev1_g[idx] + bev1_be[idx]; return; } idx -= 512;
    if (idx < 256) { g_bb2[idx] = bev2_b[idx] * bev2_g[idx] + bev2_be[idx]; return; } idx -= 256;
    if (idx < 160) { int o = idx % 32, ic = idx / 32; g_vfe1t[idx] = v1w[o * 5 + ic] * v1g[o]; return; } idx -= 160;
    if (idx < 32) { g_vfe1b[idx] = v1b[idx] * v1g[idx] + v1be[idx]; return; } idx -= 32;
    if (idx < 4096) { int o = idx % 128, ic = idx / 128; g_vfe2t[idx] = v2w[o * 32 + ic] * v2g[o]; return; } idx -= 4096;
    if (idx < 128) { g_vfe2b[idx] = v2b[idx] * v2g[idx] + v2be[idx]; return; } idx -= 128;
    if (idx < NB1) { bf_one(sp1_w, sp1_g, g_w1bfh, g_w1bfl, idx, 128, 64, 27); return; } idx -= NB1;
    if (idx < NB2) { bf_one(sp2_w, sp2_g, g_w2bfh, g_w2bfl, idx, 64, 128, 27); return; } idx -= NB2;
    if (idx < NB3) { bf_one(sp3_w, sp3_g, g_w3bfh, g_w3bfl, idx, 128, 128, 27); return; } idx -= NB3;
    if (idx < NB4) { bf_one(sp4_w, sp4_g, g_w4bfh, g_w4bfl, idx, 128, 256, 27); return; }
}

// ---------------- scan ----------------
__global__ void __launch_bounds__(1024) scan_opt() {
    __shared__ int wS[32];
    __shared__ int sBase, sTot;
    const int t = threadIdx.x, lane = t & 31, wid = t >> 5;
    if (t == 0) sBase = 0;
    __syncthreads();
    const int NIT = (NVOX + 4095) / 4096;   // 49
    int4 cur;
    {
        int base = t * 4;
        cur = (base + 3 < NVOX) ? *reinterpret_cast<const int4*>(&g_count[base])
                                : make_int4(0, 0, 0, 0);
    }
    for (int it = 0; it < NIT; it++) {
        int base = it * 4096 + t * 4;
        int4 nxt = make_int4(0, 0, 0, 0);
        if (it + 1 < NIT) {
            int nb = (it + 1) * 4096 + t * 4;
            if (nb + 3 < NVOX) nxt = *reinterpret_cast<const int4*>(&g_count[nb]);
            else {
                if (nb + 0 < NVOX) nxt.x = g_count[nb + 0];
                if (nb + 1 < NVOX) nxt.y = g_count[nb + 1];
                if (nb + 2 < NVOX) nxt.z = g_count[nb + 2];
                if (nb + 3 < NVOX) nxt.w = g_count[nb + 3];
            }
        }
        int f0 = (base + 0 < NVOX) && cur.x, f1 = (base + 1 < NVOX) && cur.y;
        int f2 = (base + 2 < NVOX) && cur.z, f3 = (base + 3 < NVOX) && cur.w;
        int tc = f0 + f1 + f2 + f3;
        int incl = tc;
#pragma unroll
        for (int o = 1; o < 32; o <<= 1) { int u = __shfl_up_sync(0xffffffffu, incl, o); if (lane >= o) incl += u; }
        if (lane == 31) wS[wid] = incl;
        __syncthreads();
        if (t < 32) {
            int v = wS[t]; int wi = v;
#pragma unroll
            for (int o = 1; o < 32; o <<= 1) { int u = __shfl_up_sync(0xffffffffu, wi, o); if (lane >= o) wi += u; }
            wS[t] = wi - v;
            if (t == 31) sTot = wi;
        }
        __syncthreads();
        int pos = sBase + wS[wid] + (incl - tc);
        int fl[4] = {f0, f1, f2, f3};
#pragma unroll
        for (int j = 0; j < 4; j++) {
            if (fl[j]) {
                int slot = pos++;
                if (slot < MAXV) {
                    int h = base + j;
                    int ix = h / (GY * GZ), r2 = h % (GY * GZ), iy = r2 / GZ, iz = r2 % GZ;
                    int cell = (iz * GY + iy) * GX + ix;
                    g_m0[cell] = 1;
                    g_list0[slot] = h;
                    g_list0cell[slot] = cell;
                }
            }
        }
        __syncthreads();
        if (t == 0) sBase += sTot;
        cur = nxt;
        __syncthreads();
    }
    if (t == 0) { int r = sBase; g_cntArr[0] = (r < MAXV) ? r : MAXV; }
}

// ---------------- VFE: warp-per-voxel; writes bf16 hi/lo features ----------
__global__ void __launch_bounds__(256) vfe_warp() {
    __shared__ float4 sW2v[32][32];
    __shared__ float sW1[5 * 32];
    __shared__ float sB1[32];
    __shared__ float4 sB2v[32];
    __shared__ float sP[8][32];
    const int t = threadIdx.x, lane = t & 31, w = t >> 5;
    for (int i = t; i < 32 * 32; i += 256) {
        int ic = i >> 5, l = i & 31;
        sW2v[ic][l] = make_float4(g_vfe2t[ic * 128 + l], g_vfe2t[ic * 128 + 32 + l],
                                  g_vfe2t[ic * 128 + 64 + l], g_vfe2t[ic * 128 + 96 + l]);
    }
    if (t < 160) sW1[t] = g_vfe1t[t];
    if (t < 32) {
        sB1[t] = g_vfe1b[t];
        sB2v[t] = make_float4(g_vfe2b[t], g_vfe2b[32 + t], g_vfe2b[64 + t], g_vfe2b[96 + t]);
    }
    __syncthreads();
    const int K = g_cntArr[0];
    const int s = blockIdx.x * 8 + w;
    if (s >= K) return;
    const int h = g_list0[s];
    const int cell = g_list0cell[s];
    int n = g_count[h]; if (n > MAXP) n = MAXP;
    const float4 b2 = sB2v[lane];
    float4 m;
    {
        sP[w][lane] = fmaxf(sB1[lane], 0.0f);
        __syncwarp();
        float4 a = b2;
#pragma unroll
        for (int ic = 0; ic < 32; ic++) {
            float pv = sP[w][ic];
            float4 wv = sW2v[ic][lane];
            a.x = fmaf(pv, wv.x, a.x); a.y = fmaf(pv, wv.y, a.y);
            a.z = fmaf(pv, wv.z, a.z); a.w = fmaf(pv, wv.w, a.w);
        }
        if (n < MAXP) {
            m = make_float4(fmaxf(a.x, 0.f), fmaxf(a.y, 0.f), fmaxf(a.z, 0.f), fmaxf(a.w, 0.f));
        } else {
            m = make_float4(-1e30f, -1e30f, -1e30f, -1e30f);
        }
    }
    for (int j = 0; j < n; j++) {
        const float* pt = g_pbuf + ((size_t)h * MAXP + j) * 5;
        float a1 = sB1[lane];
#pragma unroll
        for (int c = 0; c < 5; c++) a1 = fmaf(pt[c], sW1[c * 32 + lane], a1);
        __syncwarp();
        sP[w][lane] = fmaxf(a1, 0.0f);
        __syncwarp();
        float4 a = b2;
#pragma unroll
        for (int ic = 0; ic < 32; ic++) {
            float pv = sP[w][ic];
            float4 wv = sW2v[ic][lane];
            a.x = fmaf(pv, wv.x, a.x); a.y = fmaf(pv, wv.y, a.y);
            a.z = fmaf(pv, wv.z, a.z); a.w = fmaf(pv, wv.w, a.w);
        }
        m.x = fmaxf(m.x, fmaxf(a.x, 0.f)); m.y = fmaxf(m.y, fmaxf(a.y, 0.f));
        m.z = fmaxf(m.z, fmaxf(a.z, 0.f)); m.w = fmaxf(m.w, fmaxf(a.w, 0.f));
    }
    __nv_bfloat16* oh = g_f0h + (size_t)cell * 128;
    __nv_bfloat16* ol = g_f0l + (size_t)cell * 128;
    {
        __nv_bfloat16 hx = __float2bfloat16(m.x);
        oh[lane] = hx; ol[lane] = __float2bfloat16(m.x - __bfloat162float(hx));
        __nv_bfloat16 hy = __float2bfloat16(m.y);
        oh[32 + lane] = hy; ol[32 + lane] = __float2bfloat16(m.y - __bfloat162float(hy));
        __nv_bfloat16 hz = __float2bfloat16(m.z);
        oh[64 + lane] = hz; ol[64 + lane] = __float2bfloat16(m.z - __bfloat162float(hz));
        __nv_bfloat16 hw = __float2bfloat16(m.w);
        oh[96 + lane] = hw; ol[96 + lane] = __float2bfloat16(m.w - __bfloat162float(hw));
    }
}

// ---------------- occupancy pooling ----------------
__global__ void pool1() {
    int idx = blockIdx.x * blockDim.x + threadIdx.x;
    if (idx >= N1) return;
    int z = idx / 2500, r = idx % 2500, y = r / 50, x = r % 50;
    bool any = false;
    for (int dz = -1; dz <= 1; dz++) { int nz = 2 * z + dz; if (nz < 0 || nz >= GZ) continue;
        for (int dy = -1; dy <= 1; dy++) { int ny = 2 * y + dy; if (ny < 0 || ny >= GY) continue;
            for (int dx = -1; dx <= 1; dx++) { int nx = 2 * x + dx; if (nx < 0 || nx >= GX) continue;
                any |= (g_m0[(nz * GY + ny) * GX + nx] != 0); } } }
    if (any) { g_m1[idx] = 1; int p = atomicAdd(&g_cntArr[1], 1); g_list1[p] = idx; }
}

__global__ void pool2() {
    int idx = blockIdx.x * blockDim.x + threadIdx.x;
    if (idx >= N2) return;
    int z = idx / P2D, r = idx % P2D, y = r / 25, x = r % 25;
    bool any = false;
    for (int dz = -1; dz <= 1; dz++) { int nz = 2 * z + dz; if (nz < 0 || nz >= 10) continue;
        for (int dy = -1; dy <= 1; dy++) { int ny = 2 * y + dy; if (ny < 0 || ny >= 50) continue;
            for (int dx = -1; dx <= 1; dx++) { int nx = 2 * x + dx; if (nx < 0 || nx >= 50) continue;
                any |= (g_m1[(nz * 50 + ny) * 50 + nx] != 0); } } }
    if (any) { g_m2[idx] = 1; int p = atomicAdd(&g_cntArr[2], 1); g_list2[p] = idx; }
}

// ---------------- generic wmma bf16 sparse conv (3-pass split, cp.async) ----
template<int IC, int OCALL, int STR, int IZ, int IY, int IX, int OZ, int OY, int OX, bool SPLIT_OUT>
__global__ void __launch_bounds__(256) spconv_wmmaG(
    const __nv_bfloat16* __restrict__ fh, const __nv_bfloat16* __restrict__ fl,
    const unsigned char* __restrict__ inM,
    const __nv_bfloat16* __restrict__ wh, const __nv_bfloat16* __restrict__ wl,
    const float* __restrict__ beta,
    const int* __restrict__ listCell, int cntIdx,
    __nv_bfloat16* __restrict__ ofh, __nv_bfloat16* __restrict__ ofl,
    float* __restrict__ outF)
{
    constexpr int A_LD = IC + 8;
    constexpr int B_LD = 72;
    constexpr int KC = IC / 16;
    constexpr int CPR = IC / 8;
    constexpr int ITERS = 64 * CPR / 256;
    constexpr int RSTride = 256 / CPR;
    extern __shared__ __align__(16) char sm[];
    __nv_bfloat16* Ah = reinterpret_cast<__nv_bfloat16*>(sm);
    __nv_bfloat16* Al = Ah + 64 * A_LD;
    __nv_bfloat16* Bh = Al + 64 * A_LD;
    __nv_bfloat16* Bl = Bh + IC * B_LD;
    __shared__ int sCell[64];
    const int t = threadIdx.x, w = t >> 5;
    const int cnt = g_cntArr[cntIdx];
    const int base = blockIdx.x * 64;
    if (base >= cnt) return;
    const int oc0 = blockIdx.y * 64;
    if (t < 64) {
        int s = base + t;
        sCell[t] = (s < cnt) ? listCell[s] : -1;
    }
    __syncthreads();
    int rcz[ITERS], rcy[ITERS], rcx[ITERS];
    bool rok[ITERS];
    const int r0 = t / CPR, cchunk = t % CPR;
#pragma unroll
    for (int j = 0; j < ITERS; j++) {
        int row = r0 + j * RSTride;
        int cell = sCell[row];
        rok[j] = (cell >= 0);
        int cz = 0, cy = 0, cx = 0;
        if (cell >= 0) {
            cz = cell / (OY * OX);
            int rr = cell % (OY * OX);
            cy = rr / OX; cx = rr % OX;
        }
        rcz[j] = cz * STR; rcy[j] = cy * STR; rcx[j] = cx * STR;
    }
    // precomputed smem byte addresses
    const uint32_t aAh = s2u(Ah), aAl = s2u(Al), aBh = s2u(Bh), aBl = s2u(Bl);
    wmma::fragment<wmma::accumulator, 16, 16, 16, float> acc[2];
    wmma::fill_fragment(acc[0], 0.0f);
    wmma::fill_fragment(acc[1], 0.0f);
    const int tm = w >> 1;
    const int tn0 = (w & 1) * 2;
    for (int k = 0; k < 27; k++) {
        const int kd = k / 9 - 1, kh = (k / 3) % 3 - 1, kw = k % 3 - 1;
#pragma unroll
        for (int j = 0; j < ITERS; j++) {
            int row = r0 + j * RSTride;
            int nb = -1;
            if (rok[j]) {
                int nz = rcz[j] + kd, ny = rcy[j] + kh, nx = rcx[j] + kw;
                if (nz >= 0 && nz < IZ && ny >= 0 && ny < IY && nx >= 0 && nx < IX) {
                    int c = (nz * IY + ny) * IX + nx;
                    if (inM[c]) nb = c;
                }
            }
            uint32_t so = (uint32_t)(row * A_LD + cchunk * 8) * 2;
            unsigned ss = (nb >= 0) ? 16u : 0u;
            const __nv_bfloat16* gh = (nb >= 0) ? (fh + (size_t)nb * IC + cchunk * 8) : fh;
            const __nv_bfloat16* gl = (nb >= 0) ? (fl + (size_t)nb * IC + cchunk * 8) : fl;
            cpa16(aAh + so, gh, ss);
            cpa16(aAl + so, gl, ss);
        }
        {
            const __nv_bfloat16* sh = wh + (size_t)k * IC * OCALL + oc0;
            const __nv_bfloat16* sl = wl + (size_t)k * IC * OCALL + oc0;
            for (int i = t; i < IC * 8; i += 256) {
                int row = i >> 3, c = i & 7;
                uint32_t so = (uint32_t)(row * B_LD + c * 8) * 2;
                cpa16f(aBh + so, sh + (size_t)row * OCALL + c * 8);
                cpa16f(aBl + so, sl + (size_t)row * OCALL + c * 8);
            }
        }
        cpa_wait();
        __syncthreads();
#pragma unroll
        for (int kk = 0; kk < KC; kk++) {
            wmma::fragment<wmma::matrix_a, 16, 16, 16, __nv_bfloat16, wmma::row_major> aH, aL;
            wmma::load_matrix_sync(aH, Ah + tm * 16 * A_LD + kk * 16, A_LD);
            wmma::load_matrix_sync(aL, Al + tm * 16 * A_LD + kk * 16, A_LD);
#pragma unroll
            for (int e = 0; e < 2; e++) {
                wmma::fragment<wmma::matrix_b, 16, 16, 16, __nv_bfloat16, wmma::row_major> bH, bL;
                wmma::load_matrix_sync(bH, Bh + kk * 16 * B_LD + (tn0 + e) * 16, B_LD);
                wmma::load_matrix_sync(bL, Bl + kk * 16 * B_LD + (tn0 + e) * 16, B_LD);
                wmma::mma_sync(acc[e], aH, bH, acc[e]);
                wmma::mma_sync(acc[e], aH, bL, acc[e]);
                wmma::mma_sync(acc[e], aL, bH, acc[e]);
            }
        }
        __syncthreads();
    }
    float* Of = reinterpret_cast<float*>(sm);
    wmma::store_matrix_sync(Of + tm * 16 * 68 + (tn0 + 0) * 16, acc[0], 68, wmma::mem_row_major);
    wmma::store_matrix_sync(Of + tm * 16 * 68 + (tn0 + 1) * 16, acc[1], 68, wmma::mem_row_major);
    __syncthreads();
    for (int i = t; i < 4096; i += 256) {
        int s = i >> 6, oc = i & 63;
        int cell = sCell[s];
        if (cell >= 0) {
            float v = fmaxf(Of[s * 68 + oc] + beta[oc0 + oc], 0.0f);
            if (SPLIT_OUT) {
                __nv_bfloat16 h = __float2bfloat16(v);
                ofh[(size_t)cell * OCALL + oc0 + oc] = h;
                ofl[(size_t)cell * OCALL + oc0 + oc] = __float2bfloat16(v - __bfloat162float(h));
            } else {
                outF[(size_t)cell * OCALL + oc0 + oc] = v;
            }
        }
    }
}
template<int IC> constexpr int wsmem() {
    int a = (2 * 64 * (IC + 8) + 2 * IC * 72) * 2;
    return a > 17408 ? a : 17408;
}

// ---------------- BEV im2col (bf16 split, [p][r] layout) --------------------
__global__ void im2col1_bf(__nv_bfloat16* __restrict__ ch_, __nv_bfloat16* __restrict__ cl_) {
    int idx = blockIdx.x * blockDim.x + threadIdx.x;
    if (idx >= P2D * K1D) return;
    int p = idx / K1D;
    int r = idx % K1D;
    int k = r / 1280, chn = r % 1280;
    int ky = k / 3, kx = k % 3;
    int y = p / 25, x = p % 25;
    int sy = y + ky - 1, sx = x + kx - 1;
    float v = 0.0f;
    if (sy >= 0 && sy < 25 && sx >= 0 && sx < 25) {
        int z = chn >> 8, c = chn & 255;
        int site = z * P2D + sy * 25 + sx;
        if (g_m2[site]) v = g_feat4[(size_t)site * 256 + c];
    }
    __nv_bfloat16 h = __float2bfloat16(v);
    ch_[idx] = h;
    cl_[idx] = __float2bfloat16(v - __bfloat162float(h));
}

__global__ void im2col2_bf(__nv_bfloat16* __restrict__ ch_, __nv_bfloat16* __restrict__ cl_) {
    int idx = blockIdx.x * blockDim.x + threadIdx.x;
    if (idx >= P2D * K2D) return;
    int p = idx / K2D;
    int r = idx % K2D;
    int k = r / 512, chn = r % 512;
    int ky = k / 3, kx = k % 3;
    int y = p / 25, x = p % 25;
    int sy = y + ky - 1, sx = x + kx - 1;
    __nv_bfloat16 h = __float2bfloat16(0.f), l = h;
    if (sy >= 0 && sy < 25 && sx >= 0 && sx < 25) {
        int src = chn * P2D + sy * 25 + sx;
        h = g_bev1h[src];
        l = g_bev1l[src];
    }
    ch_[idx] = h;
    cl_[idx] = l;
}

// ---------------- BEV GEMM: wmma bf16 3-pass split, split-K, cp.async -------
template<int OCALL, int K, int SPLIT>
__global__ void __launch_bounds__(256) gemm_wmma(
    const __nv_bfloat16* __restrict__ ah_, const __nv_bfloat16* __restrict__ al_,
    const __nv_bfloat16* __restrict__ bh_, const __nv_bfloat16* __restrict__ bl_)
{
    constexpr int LD = 72;
    extern __shared__ __align__(16) char sm[];
    __nv_bfloat16* Ah = reinterpret_cast<__nv_bfloat16*>(sm);
    __nv_bfloat16* Al = Ah + 64 * LD;
    __nv_bfloat16* Bh = Al + 64 * LD;
    __nv_bfloat16* Bl = Bh + 64 * LD;
    const int t = threadIdx.x, w = t >> 5;
    const int p0 = blockIdx.x * 64, oc0 = blockIdx.y * 64;
    constexpr int KCper = K / SPLIT;
    const int kbeg = blockIdx.z * KCper;
    const uint32_t aAh = s2u(Ah), aAl = s2u(Al), aBh = s2u(Bh), aBl = s2u(Bl);
    wmma::fragment<wmma::accumulator, 16, 16, 16, float> acc[2];
    wmma::fill_fragment(acc[0], 0.0f);
    wmma::fill_fragment(acc[1], 0.0f);
    const int tm = w >> 1;
    const int tn0 = (w & 1) * 2;
    for (int k0 = kbeg; k0 < kbeg + KCper; k0 += 64) {
        for (int i = t; i < 512; i += 256) {
            int row = i >> 3, c = i & 7;
            int p = p0 + row;
            uint32_t so = (uint32_t)(row * LD + c * 8) * 2;
            unsigned ss = (p < P2D) ? 16u : 0u;
            const __nv_bfloat16* gh = (p < P2D) ? (ah_ + (size_t)p * K + k0 + c * 8) : ah_;
            const __nv_bfloat16* gl = (p < P2D) ? (al_ + (size_t)p * K + k0 + c * 8) : al_;
            cpa16(aAh + so, gh, ss);
            cpa16(aAl + so, gl, ss);
            cpa16f(aBh + so, bh_ + (size_t)(k0 + row) * OCALL + oc0 + c * 8);
            cpa16f(aBl + so, bl_ + (size_t)(k0 + row) * OCALL + oc0 + c * 8);
        }
        cpa_wait();
        __syncthreads();
#pragma unroll
        for (int kk = 0; kk < 4; kk++) {
            wmma::fragment<wmma::matrix_a, 16, 16, 16, __nv_bfloat16, wmma::row_major> aH, aL;
            wmma::load_matrix_sync(aH, Ah + tm * 16 * LD + kk * 16, LD);
            wmma::load_matrix_sync(aL, Al + tm * 16 * LD + kk * 16, LD);
#pragma unroll
            for (int e = 0; e < 2; e++) {
                wmma::fragment<wmma::matrix_b, 16, 16, 16, __nv_bfloat16, wmma::row_major> bH, bL;
                wmma::load_matrix_sync(bH, Bh + kk * 16 * LD + (tn0 + e) * 16, LD);
                wmma::load_matrix_sync(bL, Bl + kk * 16 * LD + (tn0 + e) * 16, LD);
                wmma::mma_sync(acc[e], aH, bH, acc[e]);
                wmma::mma_sync(acc[e], aH, bL, acc[e]);
                wmma::mma_sync(acc[e], aL, bH, acc[e]);
            }
        }
        __syncthreads();
    }
    float* Of = reinterpret_cast<float*>(sm);
    wmma::store_matrix_sync(Of + tm * 16 * 68 + (tn0 + 0) * 16, acc[0], 68, wmma::mem_row_major);
    wmma::store_matrix_sync(Of + tm * 16 * 68 + (tn0 + 1) * 16, acc[1], 68, wmma::mem_row_major);
    __syncthreads();
    float* gp = g_part + (size_t)blockIdx.z * OCALL * P2D;
    for (int i = t; i < 4096; i += 256) {
        int row = i >> 6, oc = i & 63;
        int p = p0 + row;
        if (p < P2D) gp[(size_t)(oc0 + oc) * P2D + p] = Of[row * 68 + oc];
    }
}
static constexpr int GEMM_SMEM = 4 * 64 * 72 * 2;   // 36864

// combine gemm1 partials -> bias+relu -> bf16 split bev1
__global__ void combine1_bf(const float* __restrict__ bias) {
    int idx = blockIdx.x * blockDim.x + threadIdx.x;
    if (idx >= 512 * P2D) return;
    int oc = idx / P2D;
    float s = bias[oc];
#pragma unroll
    for (int z = 0; z < 4; z++) s += g_part[(size_t)z * 512 * P2D + idx];
    float v = fmaxf(s, 0.0f);
    __nv_bfloat16 h = __float2bfloat16(v);
    g_bev1h[idx] = h;
    g_bev1l[idx] = __float2bfloat16(v - __bfloat162float(h));
}

// final: combine2 + re-zero all state for next call
static constexpr int COMB2_BLOCKS = (256 * P2D + 255) / 256;
static constexpr int ZC0 = NVOX;
static constexpr int ZC1 = NVOX / 4;
static constexpr int ZC2 = N1 / 4;
static constexpr int ZC3 = N2;
static constexpr int ZTOT = ZC0 + ZC1 + ZC2 + ZC3 + 3;
static constexpr int ZBLK = (ZTOT + 255) / 256;

__global__ void final_combine_zero(const float* __restrict__ bias, float* __restrict__ out) {
    if (blockIdx.x < COMB2_BLOCKS) {
        int idx = blockIdx.x * 256 + threadIdx.x;
        if (idx >= 256 * P2D) return;
        int oc = idx / P2D;
        float s = bias[oc];
#pragma unroll
        for (int z = 0; z < 4; z++) s += g_part[(size_t)z * 256 * P2D + idx];
        out[idx] = fmaxf(s, 0.0f);
        return;
    }
    int idx = (blockIdx.x - COMB2_BLOCKS) * 256 + threadIdx.x;
    if (idx < ZC0) { g_count[idx] = 0; return; } idx -= ZC0;
    if (idx < ZC1) { reinterpret_cast<int*>(g_m0)[idx] = 0; return; } idx -= ZC1;
    if (idx < ZC2) { reinterpret_cast<int*>(g_m1)[idx] = 0; return; } idx -= ZC2;
    if (idx < ZC3) { g_m2[idx] = 0; return; } idx -= ZC3;
    if (idx < 3) { g_cntArr[idx] = 0; return; }
}

// ---------------- host ----------------
static inline void* sym(const void* s) { void* p = nullptr; cudaGetSymbolAddress(&p, s); return p; }

extern "C" void kernel_launch(void* const* d_in, const int* in_sizes, int n_in,
                              void* d_out, int out_size) {
    const float* points = (const float*)d_in[0];
    const float *vfe1_w = (const float*)d_in[1], *vfe1_b = (const float*)d_in[2],
                *vfe1_g = (const float*)d_in[3], *vfe1_be = (const float*)d_in[4];
    const float *vfe2_w = (const float*)d_in[5], *vfe2_b = (const float*)d_in[6],
                *vfe2_g = (const float*)d_in[7], *vfe2_be = (const float*)d_in[8];
    const float *sp1_w = (const float*)d_in[9],  *sp1_g = (const float*)d_in[10], *sp1_be = (const float*)d_in[11];
    const float *sp2_w = (const float*)d_in[12], *sp2_g = (const float*)d_in[13], *sp2_be = (const float*)d_in[14];
    const float *sp3_w = (const float*)d_in[15], *sp3_g = (const float*)d_in[16], *sp3_be = (const float*)d_in[17];
    const float *sp4_w = (const float*)d_in[18], *sp4_g = (const float*)d_in[19], *sp4_be = (const float*)d_in[20];
    const float *bev1_w = (const float*)d_in[21], *bev1_b = (const float*)d_in[22],
                *bev1_g = (const float*)d_in[23], *bev1_be = (const float*)d_in[24];
    const float *bev2_w = (const float*)d_in[25], *bev2_b = (const float*)d_in[26],
                *bev2_g = (const float*)d_in[27], *bev2_be = (const float*)d_in[28];

    int Npts = in_sizes[0] / 5;

    float* bb1 = (float*)sym(g_bb1);  float* bb2 = (float*)sym(g_bb2);
    unsigned char* m0 = (unsigned char*)sym(g_m0);
    unsigned char* m1 = (unsigned char*)sym(g_m1);
    int* l0c = (int*)sym(g_list0cell);
    int* l1 = (int*)sym(g_list1); int* l2 = (int*)sym(g_list2);
    const __nv_bfloat16* f0h = (const __nv_bfloat16*)sym(g_f0h);
    const __nv_bfloat16* f0l = (const __nv_bfloat16*)sym(g_f0l);
    __nv_bfloat16* f1h = (__nv_bfloat16*)sym(g_f1h);
    __nv_bfloat16* f1l = (__nv_bfloat16*)sym(g_f1l);
    __nv_bfloat16* f2h = (__nv_bfloat16*)sym(g_f2h);
    __nv_bfloat16* f2l = (__nv_bfloat16*)sym(g_f2l);
    __nv_bfloat16* f3h = (__nv_bfloat16*)sym(g_f3h);
    __nv_bfloat16* f3l = (__nv_bfloat16*)sym(g_f3l);
    const __nv_bfloat16* w1h = (const __nv_bfloat16*)sym(g_w1bfh);
    const __nv_bfloat16* w1l = (const __nv_bfloat16*)sym(g_w1bfl);
    const __nv_bfloat16* w2h = (const __nv_bfloat16*)sym(g_w2bfh);
    const __nv_bfloat16* w2l = (const __nv_bfloat16*)sym(g_w2bfl);
    const __nv_bfloat16* w3h = (const __nv_bfloat16*)sym(g_w3bfh);
    const __nv_bfloat16* w3l = (const __nv_bfloat16*)sym(g_w3bfl);
    const __nv_bfloat16* w4h = (const __nv_bfloat16*)sym(g_w4bfh);
    const __nv_bfloat16* w4l = (const __nv_bfloat16*)sym(g_w4bfl);
    __nv_bfloat16* c1h = (__nv_bfloat16*)sym(g_col1h);
    __nv_bfloat16* c1l = (__nv_bfloat16*)sym(g_col1l);
    __nv_bfloat16* c2h = (__nv_bfloat16*)sym(g_col2h);
    __nv_bfloat16* c2l = (__nv_bfloat16*)sym(g_col2l);
    const __nv_bfloat16* wb1h = (const __nv_bfloat16*)sym(g_wb1h);
    const __nv_bfloat16* wb1l = (const __nv_bfloat16*)sym(g_wb1l);
    const __nv_bfloat16* wb2h = (const __nv_bfloat16*)sym(g_wb2h);
    const __nv_bfloat16* wb2l = (const __nv_bfloat16*)sym(g_wb2l);

    auto k1 = spconv_wmmaG<128, 64, 1, 20, 100, 100, 20, 100, 100, true>;
    auto k2 = spconv_wmmaG<64, 128, 2, 20, 100, 100, 10, 50, 50, true>;
    auto k3 = spconv_wmmaG<128, 128, 1, 10, 50, 50, 10, 50, 50, true>;
    auto k4 = spconv_wmmaG<128, 256, 2, 10, 50, 50, 5, 25, 25, false>;
    cudaFuncSetAttribute(k1, cudaFuncAttributeMaxDynamicSharedMemorySize, wsmem<128>());
    cudaFuncSetAttribute(k2, cudaFuncAttributeMaxDynamicSharedMemorySize, wsmem<64>());
    cudaFuncSetAttribute(k3, cudaFuncAttributeMaxDynamicSharedMemorySize, wsmem<128>());
    cudaFuncSetAttribute(k4, cudaFuncAttributeMaxDynamicSharedMemorySize, wsmem<128>());

    // 0: scatter + weight prep
    scatter_prep<<<SCAT_BLOCKS + PREP_BLOCKS, 256>>>(
        points, Npts,
        sp1_w, sp1_g, sp2_w, sp2_g, sp3_w, sp3_g, sp4_w, sp4_g,
        bev1_w, bev1_g, bev2_w, bev2_g, bev1_b, bev1_be, bev2_b, bev2_be,
        vfe1_w, vfe1_b, vfe1_g, vfe1_be, vfe2_w, vfe2_b, vfe2_g, vfe2_be);
    // 1: scan
    scan_opt<<<1, 1024>>>();
    // 2: VFE
    vfe_warp<<<(MAXV + 7) / 8, 256>>>();
    // 3: sp1 wmma (profiled launch)
    {
        dim3 g((MAXV + 63) / 64, 1);
        k1<<<g, 256, wsmem<128>()>>>(f0h, f0l, m0, w1h, w1l, sp1_be, l0c, 0,
                                     f1h, f1l, nullptr);
    }
    // 4:
    pool1<<<(N1 + 255) / 256, 256>>>();
    // 5: sp2 wmma
    {
        dim3 g((N1 + 63) / 64, 2);
        k2<<<g, 256, wsmem<64>()>>>(f1h, f1l, m0, w2h, w2l, sp2_be, l1, 1,
                                    f2h, f2l, nullptr);
    }
    // 6: sp3 wmma
    {
        dim3 g((N1 + 63) / 64, 2);
        k3<<<g, 256, wsmem<128>()>>>(f2h, f2l, m1, w3h, w3l, sp3_be, l1, 1,
                                     f3h, f3l, nullptr);
    }
    // 7:
    pool2<<<(N2 + 255) / 256, 256>>>();
    // 8: sp4 wmma (float out)
    {
        dim3 g((N2 + 63) / 64, 4);
        k4<<<g, 256, wsmem<128>()>>>(f3h, f3l, m1, w4h, w4l, sp4_be, l2, 2,
                                     nullptr, nullptr, (float*)sym(g_feat4));
    }
    // 9: im2col1 (bf16 split)
    im2col1_bf<<<(P2D * K1D + 255) / 256, 256>>>(c1h, c1l);
    // 10: gemm1 wmma
    {
        dim3 g((P2D + 63) / 64, 512 / 64, 4);
        gemm_wmma<512, K1D, 4><<<g, 256, GEMM_SMEM>>>(c1h, c1l, wb1h, wb1l);
    }
    // 11: combine1 -> bf16 split
    combine1_bf<<<(512 * P2D + 255) / 256, 256>>>(bb1);
    // 12: im2col2 (bf16 copy)
    im2col2_bf<<<(P2D * K2D + 255) / 256, 256>>>(c2h, c2l);
    // 13: gemm2 wmma
    {
        dim3 g((P2D + 63) / 64, 256 / 64, 4);
        gemm_wmma<256, K2D, 4><<<g, 256, GEMM_SMEM>>>(c2h, c2l, wb2h, wb2l);
    }
    // 14: combine2 + re-zero state
    final_combine_zero<<<COMB2_BLOCKS + ZBLK, 256>>>(bb2, (float*)d_out);
}

// round 17
// speedup vs baseline: 1.0733x; 1.0733x over previous
#include <cuda_runtime.h>
#include <cuda_bf16.h>
#include <mma.h>
#include <cstdint>

using namespace nvcuda;

// ---------------- constants ----------------
static constexpr int GX = 100, GY = 100, GZ = 20;
static constexpr int NVOX = GX * GY * GZ;            // 200000
static constexpr int MAXV = 60000, MAXP = 10;
static constexpr int N1 = 10 * 50 * 50;              // 25000
static constexpr int N2 = 5 * 25 * 25;               // 3125
static constexpr int P2D = 625;                      // 25*25
static constexpr int K1D = 11520;                    // 9*1280
static constexpr int K2D = 4608;                     // 9*512

// ---------------- device scratch ----------------
__device__ int           g_count[NVOX];
__device__ float         g_pbuf[(size_t)NVOX * MAXP * 5];
__device__ unsigned char g_m0[NVOX];
__device__ unsigned char g_m1[N1];
__device__ unsigned char g_m2[N2];
__device__ int           g_list0[MAXV];
__device__ int           g_list0cell[MAXV];
__device__ int           g_list1[N1];
__device__ int           g_list2[N2];
__device__ int           g_cntArr[3];

__device__ __align__(16) __nv_bfloat16 g_f0h[(size_t)NVOX * 128];
__device__ __align__(16) __nv_bfloat16 g_f0l[(size_t)NVOX * 128];
__device__ __align__(16) __nv_bfloat16 g_f1h[(size_t)NVOX * 64];
__device__ __align__(16) __nv_bfloat16 g_f1l[(size_t)NVOX * 64];
__device__ __align__(16) __nv_bfloat16 g_f2h[(size_t)N1 * 128];
__device__ __align__(16) __nv_bfloat16 g_f2l[(size_t)N1 * 128];
__device__ __align__(16) __nv_bfloat16 g_f3h[(size_t)N1 * 128];
__device__ __align__(16) __nv_bfloat16 g_f3l[(size_t)N1 * 128];
__device__ float g_feat4[(size_t)N2 * 256];
__device__ __align__(16) __nv_bfloat16 g_col1h[(size_t)P2D * K1D];
__device__ __align__(16) __nv_bfloat16 g_col1l[(size_t)P2D * K1D];
__device__ __align__(16) __nv_bfloat16 g_col2h[(size_t)P2D * K2D];
__device__ __align__(16) __nv_bfloat16 g_col2l[(size_t)P2D * K2D];
__device__ __align__(16) __nv_bfloat16 g_bev1h[(size_t)512 * P2D];
__device__ __align__(16) __nv_bfloat16 g_bev1l[(size_t)512 * P2D];
__device__ float g_part[(size_t)4 * 512 * P2D];

__device__ float g_vfe1t[5 * 32], g_vfe1b[32];
__device__ float g_vfe2t[32 * 128], g_vfe2b[128];
__device__ float g_bb1[512], g_bb2[256];
// bf16 split conv weights, [k][ic][oc] row-major
__device__ __align__(16) __nv_bfloat16 g_w1bfh[27 * 128 * 64];
__device__ __align__(16) __nv_bfloat16 g_w1bfl[27 * 128 * 64];
__device__ __align__(16) __nv_bfloat16 g_w2bfh[27 * 64 * 128];
__device__ __align__(16) __nv_bfloat16 g_w2bfl[27 * 64 * 128];
__device__ __align__(16) __nv_bfloat16 g_w3bfh[27 * 128 * 128];
__device__ __align__(16) __nv_bfloat16 g_w3bfl[27 * 128 * 128];
__device__ __align__(16) __nv_bfloat16 g_w4bfh[27 * 128 * 256];
__device__ __align__(16) __nv_bfloat16 g_w4bfl[27 * 128 * 256];
// bf16 split BEV weights, [r][oc] row-major
__device__ __align__(16) __nv_bfloat16 g_wb1h[(size_t)K1D * 512];
__device__ __align__(16) __nv_bfloat16 g_wb1l[(size_t)K1D * 512];
__device__ __align__(16) __nv_bfloat16 g_wb2h[(size_t)K2D * 256];
__device__ __align__(16) __nv_bfloat16 g_wb2l[(size_t)K2D * 256];

// ---------------- cp.async helpers ----------------
__device__ __forceinline__ uint32_t s2u(const void* p) {
    uint32_t a;
    asm("{ .reg .u64 t; cvta.to.shared.u64 t, %1; cvt.u32.u64 %0, t; }" : "=r"(a) : "l"(p));
    return a;
}
__device__ __forceinline__ void cpa16(uint32_t saddr, const void* g, unsigned srcsize) {
    asm volatile("cp.async.cg.shared.global [%0], [%1], 16, %2;"
                 :: "r"(saddr), "l"(g), "r"(srcsize));
}
__device__ __forceinline__ void cpa16f(uint32_t saddr, const void* g) {
    asm volatile("cp.async.cg.shared.global [%0], [%1], 16;"
                 :: "r"(saddr), "l"(g));
}
__device__ __forceinline__ void cpa_wait() {
    asm volatile("cp.async.commit_group;\ncp.async.wait_group 0;" ::: "memory");
}

// ---------------- fused scatter + weight prep ----------------
static constexpr int SCAT_BLOCKS = (250000 + 255) / 256;
// dst-linear split (coalesced writes): idx = (k*I+ic)*O+oc
__device__ __forceinline__ void bf_one(const float* __restrict__ src, const float* __restrict__ g,
                                       __nv_bfloat16* __restrict__ dh, __nv_bfloat16* __restrict__ dl,
                                       int idx, int I, int O, int KK) {
    int oc = idx % O;
    int rest = idx / O;
    int ic = rest % I;
    int k = rest / I;
    float w = src[((size_t)oc * I + ic) * KK + k] * g[oc];
    __nv_bfloat16 h = __float2bfloat16(w);
    dh[idx] = h;
    dl[idx] = __float2bfloat16(w - __bfloat162float(h));
}

static constexpr int NB1 = 27 * 128 * 64, NB2 = 27 * 64 * 128, NB3 = 27 * 128 * 128, NB4 = 27 * 128 * 256;
static constexpr int NW1 = K1D * 512, NW2 = K2D * 256;
static constexpr int PREP_TOTAL = NW1 + NW2 + 512 + 256 + 160 + 32 + 4096 + 128
                                + NB1 + NB2 + NB3 + NB4;
static constexpr int PREP_BLOCKS = (PREP_TOTAL + 255) / 256;

__global__ void __launch_bounds__(256) scatter_prep(
    const float* __restrict__ pts, int N,
    const float* __restrict__ sp1_w, const float* __restrict__ sp1_g,
    const float* __restrict__ sp2_w, const float* __restrict__ sp2_g,
    const float* __restrict__ sp3_w, const float* __restrict__ sp3_g,
    const float* __restrict__ sp4_w, const float* __restrict__ sp4_g,
    const float* __restrict__ bev1_w, const float* __restrict__ bev1_g,
    const float* __restrict__ bev2_w, const float* __restrict__ bev2_g,
    const float* __restrict__ bev1_b, const float* __restrict__ bev1_be,
    const float* __restrict__ bev2_b, const float* __restrict__ bev2_be,
    const float* __restrict__ v1w, const float* __restrict__ v1b,
    const float* __restrict__ v1g, const float* __restrict__ v1be,
    const float* __restrict__ v2w, const float* __restrict__ v2b,
    const float* __restrict__ v2g, const float* __restrict__ v2be)
{
    if (blockIdx.x < SCAT_BLOCKS) {
        int i = blockIdx.x * 256 + threadIdx.x;
        if (i >= N) return;
        const float* p = pts + (size_t)i * 5;
        float x = p[0], y = p[1], z = p[2];
        if (x == 0.0f) return;
        int ix = (int)floorf(__fdiv_rn(__fsub_rn(x, -51.2f), 1.024f));
        int iy = (int)floorf(__fdiv_rn(__fsub_rn(y, -51.2f), 1.024f));
        int iz = (int)floorf(__fdiv_rn(__fsub_rn(z, -5.0f), 0.4f));
        if (ix < 0 || ix >= GX || iy < 0 || iy >= GY || iz < 0 || iz >= GZ) return;
        int h = ix * (GY * GZ) + iy * GZ + iz;
        int r = atomicAdd(&g_count[h], 1);
        if (r < MAXP) {
            float* d = g_pbuf + ((size_t)h * MAXP + r) * 5;
            d[0] = x; d[1] = y; d[2] = z; d[3] = p[3]; d[4] = p[4];
        }
        return;
    }
    int idx = (blockIdx.x - SCAT_BLOCKS) * 256 + threadIdx.x;
    if (idx < NW1) { bf_one(bev1_w, bev1_g, g_wb1h, g_wb1l, idx, 1280, 512, 9); return; } idx -= NW1;
    if (idx < NW2) { bf_one(bev2_w, bev2_g, g_wb2h, g_wb2l, idx, 512, 256, 9); return; } idx -= NW2;
    if (idx < 512) { g_bb1[idx] = bev1_b[idx] * bev1_g[idx] + bev1_be[idx]; return; } idx -= 512;
    if (idx < 256) { g_bb2[idx] = bev2_b[idx] * bev2_g[idx] + bev2_be[idx]; return; } idx -= 256;
    if (idx < 160) { int o = idx % 32, ic = idx / 32; g_vfe1t[idx] = v1w[o * 5 + ic] * v1g[o]; return; } idx -= 160;
    if (idx < 32) { g_vfe1b[idx] = v1b[idx] * v1g[idx] + v1be[idx]; return; } idx -= 32;
    if (idx < 4096) { int o = idx % 128, ic = idx / 128; g_vfe2t[idx] = v2w[o * 32 + ic] * v2g[o]; return; } idx -= 4096;
    if (idx < 128) { g_vfe2b[idx] = v2b[idx] * v2g[idx] + v2be[idx]; return; } idx -= 128;
    if (idx < NB1) { bf_one(sp1_w, sp1_g, g_w1bfh, g_w1bfl, idx, 128, 64, 27); return; } idx -= NB1;
    if (idx < NB2) { bf_one(sp2_w, sp2_g, g_w2bfh, g_w2bfl, idx, 64, 128, 27); return; } idx -= NB2;
    if (idx < NB3) { bf_one(sp3_w, sp3_g, g_w3bfh, g_w3bfl, idx, 128, 128, 27); return; } idx -= NB3;
    if (idx < NB4) { bf_one(sp4_w, sp4_g, g_w4bfh, g_w4bfl, idx, 128, 256, 27); return; }
}

// ---------------- scan ----------------
__global__ void __launch_bounds__(1024) scan_opt() {
    __shared__ int wS[32];
    __shared__ int sBase, sTot;
    const int t = threadIdx.x, lane = t & 31, wid = t >> 5;
    if (t == 0) sBase = 0;
    __syncthreads();
    const int NIT = (NVOX + 4095) / 4096;   // 49
    int4 cur;
    {
        int base = t * 4;
        cur = (base + 3 < NVOX) ? *reinterpret_cast<const int4*>(&g_count[base])
                                : make_int4(0, 0, 0, 0);
    }
    for (int it = 0; it < NIT; it++) {
        int base = it * 4096 + t * 4;
        int4 nxt = make_int4(0, 0, 0, 0);
        if (it + 1 < NIT) {
            int nb = (it + 1) * 4096 + t * 4;
            if (nb + 3 < NVOX) nxt = *reinterpret_cast<const int4*>(&g_count[nb]);
            else {
                if (nb + 0 < NVOX) nxt.x = g_count[nb + 0];
                if (nb + 1 < NVOX) nxt.y = g_count[nb + 1];
                if (nb + 2 < NVOX) nxt.z = g_count[nb + 2];
                if (nb + 3 < NVOX) nxt.w = g_count[nb + 3];
            }
        }
        int f0 = (base + 0 < NVOX) && cur.x, f1 = (base + 1 < NVOX) && cur.y;
        int f2 = (base + 2 < NVOX) && cur.z, f3 = (base + 3 < NVOX) && cur.w;
        int tc = f0 + f1 + f2 + f3;
        int incl = tc;
#pragma unroll
        for (int o = 1; o < 32; o <<= 1) { int u = __shfl_up_sync(0xffffffffu, incl, o); if (lane >= o) incl += u; }
        if (lane == 31) wS[wid] = incl;
        __syncthreads();
        if (t < 32) {
            int v = wS[t]; int wi = v;
#pragma unroll
            for (int o = 1; o < 32; o <<= 1) { int u = __shfl_up_sync(0xffffffffu, wi, o); if (lane >= o) wi += u; }
            wS[t] = wi - v;
            if (t == 31) sTot = wi;
        }
        __syncthreads();
        int pos = sBase + wS[wid] + (incl - tc);
        int fl[4] = {f0, f1, f2, f3};
#pragma unroll
        for (int j = 0; j < 4; j++) {
            if (fl[j]) {
                int slot = pos++;
                if (slot < MAXV) {
                    int h = base + j;
                    int ix = h / (GY * GZ), r2 = h % (GY * GZ), iy = r2 / GZ, iz = r2 % GZ;
                    int cell = (iz * GY + iy) * GX + ix;
                    g_m0[cell] = 1;
                    g_list0[slot] = h;
                    g_list0cell[slot] = cell;
                }
            }
        }
        __syncthreads();
        if (t == 0) sBase += sTot;
        cur = nxt;
        __syncthreads();
    }
    if (t == 0) { int r = sBase; g_cntArr[0] = (r < MAXV) ? r : MAXV; }
}

// ---------------- VFE: warp-per-voxel; writes bf16 hi/lo features ----------
__global__ void __launch_bounds__(256) vfe_warp() {
    __shared__ float4 sW2v[32][32];
    __shared__ float sW1[5 * 32];
    __shared__ float sB1[32];
    __shared__ float4 sB2v[32];
    __shared__ float sP[8][32];
    const int t = threadIdx.x, lane = t & 31, w = t >> 5;
    for (int i = t; i < 32 * 32; i += 256) {
        int ic = i >> 5, l = i & 31;
        sW2v[ic][l] = make_float4(g_vfe2t[ic * 128 + l], g_vfe2t[ic * 128 + 32 + l],
                                  g_vfe2t[ic * 128 + 64 + l], g_vfe2t[ic * 128 + 96 + l]);
    }
    if (t < 160) sW1[t] = g_vfe1t[t];
    if (t < 32) {
        sB1[t] = g_vfe1b[t];
        sB2v[t] = make_float4(g_vfe2b[t], g_vfe2b[32 + t], g_vfe2b[64 + t], g_vfe2b[96 + t]);
    }
    __syncthreads();
    const int K = g_cntArr[0];
    const int s = blockIdx.x * 8 + w;
    if (s >= K) return;
    const int h = g_list0[s];
    const int cell = g_list0cell[s];
    int n = g_count[h]; if (n > MAXP) n = MAXP;
    const float4 b2 = sB2v[lane];
    float4 m;
    {
        sP[w][lane] = fmaxf(sB1[lane], 0.0f);
        __syncwarp();
        float4 a = b2;
#pragma unroll
        for (int ic = 0; ic < 32; ic++) {
            float pv = sP[w][ic];
            float4 wv = sW2v[ic][lane];
            a.x = fmaf(pv, wv.x, a.x); a.y = fmaf(pv, wv.y, a.y);
            a.z = fmaf(pv, wv.z, a.z); a.w = fmaf(pv, wv.w, a.w);
        }
        if (n < MAXP) {
            m = make_float4(fmaxf(a.x, 0.f), fmaxf(a.y, 0.f), fmaxf(a.z, 0.f), fmaxf(a.w, 0.f));
        } else {
            m = make_float4(-1e30f, -1e30f, -1e30f, -1e30f);
        }
    }
    for (int j = 0; j < n; j++) {
        const float* pt = g_pbuf + ((size_t)h * MAXP + j) * 5;
        float a1 = sB1[lane];
#pragma unroll
        for (int c = 0; c < 5; c++) a1 = fmaf(pt[c], sW1[c * 32 + lane], a1);
        __syncwarp();
        sP[w][lane] = fmaxf(a1, 0.0f);
        __syncwarp();
        float4 a = b2;
#pragma unroll
        for (int ic = 0; ic < 32; ic++) {
            float pv = sP[w][ic];
            float4 wv = sW2v[ic][lane];
            a.x = fmaf(pv, wv.x, a.x); a.y = fmaf(pv, wv.y, a.y);
            a.z = fmaf(pv, wv.z, a.z); a.w = fmaf(pv, wv.w, a.w);
        }
        m.x = fmaxf(m.x, fmaxf(a.x, 0.f)); m.y = fmaxf(m.y, fmaxf(a.y, 0.f));
        m.z = fmaxf(m.z, fmaxf(a.z, 0.f)); m.w = fmaxf(m.w, fmaxf(a.w, 0.f));
    }
    __nv_bfloat16* oh = g_f0h + (size_t)cell * 128;
    __nv_bfloat16* ol = g_f0l + (size_t)cell * 128;
    {
        __nv_bfloat16 hx = __float2bfloat16(m.x);
        oh[lane] = hx; ol[lane] = __float2bfloat16(m.x - __bfloat162float(hx));
        __nv_bfloat16 hy = __float2bfloat16(m.y);
        oh[32 + lane] = hy; ol[32 + lane] = __float2bfloat16(m.y - __bfloat162float(hy));
        __nv_bfloat16 hz = __float2bfloat16(m.z);
        oh[64 + lane] = hz; ol[64 + lane] = __float2bfloat16(m.z - __bfloat162float(hz));
        __nv_bfloat16 hw = __float2bfloat16(m.w);
        oh[96 + lane] = hw; ol[96 + lane] = __float2bfloat16(m.w - __bfloat162float(hw));
    }
}

// ---------------- occupancy pooling ----------------
__global__ void pool1() {
    int idx = blockIdx.x * blockDim.x + threadIdx.x;
    if (idx >= N1) return;
    int z = idx / 2500, r = idx % 2500, y = r / 50, x = r % 50;
    bool any = false;
    for (int dz = -1; dz <= 1; dz++) { int nz = 2 * z + dz; if (nz < 0 || nz >= GZ) continue;
        for (int dy = -1; dy <= 1; dy++) { int ny = 2 * y + dy; if (ny < 0 || ny >= GY) continue;
            for (int dx = -1; dx <= 1; dx++) { int nx = 2 * x + dx; if (nx < 0 || nx >= GX) continue;
                any |= (g_m0[(nz * GY + ny) * GX + nx] != 0); } } }
    if (any) { g_m1[idx] = 1; int p = atomicAdd(&g_cntArr[1], 1); g_list1[p] = idx; }
}

__global__ void pool2() {
    int idx = blockIdx.x * blockDim.x + threadIdx.x;
    if (idx >= N2) return;
    int z = idx / P2D, r = idx % P2D, y = r / 25, x = r % 25;
    bool any = false;
    for (int dz = -1; dz <= 1; dz++) { int nz = 2 * z + dz; if (nz < 0 || nz >= 10) continue;
        for (int dy = -1; dy <= 1; dy++) { int ny = 2 * y + dy; if (ny < 0 || ny >= 50) continue;
            for (int dx = -1; dx <= 1; dx++) { int nx = 2 * x + dx; if (nx < 0 || nx >= 50) continue;
                any |= (g_m1[(nz * 50 + ny) * 50 + nx] != 0); } } }
    if (any) { g_m2[idx] = 1; int p = atomicAdd(&g_cntArr[2], 1); g_list2[p] = idx; }
}

// ---------------- generic wmma bf16 sparse conv (3-pass split, cp.async) ----
template<int IC, int OCALL, int STR, int IZ, int IY, int IX, int OZ, int OY, int OX, bool SPLIT_OUT>
__global__ void __launch_bounds__(256) spconv_wmmaG(
    const __nv_bfloat16* __restrict__ fh, const __nv_bfloat16* __restrict__ fl,
    const unsigned char* __restrict__ inM,
    const __nv_bfloat16* __restrict__ wh, const __nv_bfloat16* __restrict__ wl,
    const float* __restrict__ beta,
    const int* __restrict__ listCell, int cntIdx,
    __nv_bfloat16* __restrict__ ofh, __nv_bfloat16* __restrict__ ofl,
    float* __restrict__ outF)
{
    constexpr int A_LD = IC + 8;
    constexpr int B_LD = 72;
    constexpr int KC = IC / 16;
    constexpr int CPR = IC / 8;
    constexpr int ITERS = 64 * CPR / 256;
    constexpr int RSTride = 256 / CPR;
    extern __shared__ __align__(16) char sm[];
    __nv_bfloat16* Ah = reinterpret_cast<__nv_bfloat16*>(sm);
    __nv_bfloat16* Al = Ah + 64 * A_LD;
    __nv_bfloat16* Bh = Al + 64 * A_LD;
    __nv_bfloat16* Bl = Bh + IC * B_LD;
    __shared__ int sCell[64];
    const int t = threadIdx.x, w = t >> 5;
    const int cnt = g_cntArr[cntIdx];
    const int base = blockIdx.x * 64;
    if (base >= cnt) return;
    const int oc0 = blockIdx.y * 64;
    if (t < 64) {
        int s = base + t;
        sCell[t] = (s < cnt) ? listCell[s] : -1;
    }
    __syncthreads();
    int rcz[ITERS], rcy[ITERS], rcx[ITERS];
    bool rok[ITERS];
    const int r0 = t / CPR, cchunk = t % CPR;
#pragma unroll
    for (int j = 0; j < ITERS; j++) {
        int row = r0 + j * RSTride;
        int cell = sCell[row];
        rok[j] = (cell >= 0);
        int cz = 0, cy = 0, cx = 0;
        if (cell >= 0) {
            cz = cell / (OY * OX);
            int rr = cell % (OY * OX);
            cy = rr / OX; cx = rr % OX;
        }
        rcz[j] = cz * STR; rcy[j] = cy * STR; rcx[j] = cx * STR;
    }
    const uint32_t aAh = s2u(Ah), aAl = s2u(Al), aBh = s2u(Bh), aBl = s2u(Bl);
    wmma::fragment<wmma::accumulator, 16, 16, 16, float> acc[2];
    wmma::fill_fragment(acc[0], 0.0f);
    wmma::fill_fragment(acc[1], 0.0f);
    const int tm = w >> 1;
    const int tn0 = (w & 1) * 2;
    for (int k = 0; k < 27; k++) {
        const int kd = k / 9 - 1, kh = (k / 3) % 3 - 1, kw = k % 3 - 1;
#pragma unroll
        for (int j = 0; j < ITERS; j++) {
            int row = r0 + j * RSTride;
            int nb = -1;
            if (rok[j]) {
                int nz = rcz[j] + kd, ny = rcy[j] + kh, nx = rcx[j] + kw;
                if (nz >= 0 && nz < IZ && ny >= 0 && ny < IY && nx >= 0 && nx < IX) {
                    int c = (nz * IY + ny) * IX + nx;
                    if (inM[c]) nb = c;
                }
            }
            uint32_t so = (uint32_t)(row * A_LD + cchunk * 8) * 2;
            unsigned ss = (nb >= 0) ? 16u : 0u;
            const __nv_bfloat16* gh = (nb >= 0) ? (fh + (size_t)nb * IC + cchunk * 8) : fh;
            const __nv_bfloat16* gl = (nb >= 0) ? (fl + (size_t)nb * IC + cchunk * 8) : fl;
            cpa16(aAh + so, gh, ss);
            cpa16(aAl + so, gl, ss);
        }
        {
            const __nv_bfloat16* sh = wh + (size_t)k * IC * OCALL + oc0;
            const __nv_bfloat16* sl = wl + (size_t)k * IC * OCALL + oc0;
            for (int i = t; i < IC * 8; i += 256) {
                int row = i >> 3, c = i & 7;
                uint32_t so = (uint32_t)(row * B_LD + c * 8) * 2;
                cpa16f(aBh + so, sh + (size_t)row * OCALL + c * 8);
                cpa16f(aBl + so, sl + (size_t)row * OCALL + c * 8);
            }
        }
        cpa_wait();
        __syncthreads();
#pragma unroll
        for (int kk = 0; kk < KC; kk++) {
            wmma::fragment<wmma::matrix_a, 16, 16, 16, __nv_bfloat16, wmma::row_major> aH, aL;
            wmma::load_matrix_sync(aH, Ah + tm * 16 * A_LD + kk * 16, A_LD);
            wmma::load_matrix_sync(aL, Al + tm * 16 * A_LD + kk * 16, A_LD);
#pragma unroll
            for (int e = 0; e < 2; e++) {
                wmma::fragment<wmma::matrix_b, 16, 16, 16, __nv_bfloat16, wmma::row_major> bH, bL;
                wmma::load_matrix_sync(bH, Bh + kk * 16 * B_LD + (tn0 + e) * 16, B_LD);
                wmma::load_matrix_sync(bL, Bl + kk * 16 * B_LD + (tn0 + e) * 16, B_LD);
                wmma::mma_sync(acc[e], aH, bH, acc[e]);
                wmma::mma_sync(acc[e], aH, bL, acc[e]);
                wmma::mma_sync(acc[e], aL, bH, acc[e]);
            }
        }
        __syncthreads();
    }
    float* Of = reinterpret_cast<float*>(sm);
    wmma::store_matrix_sync(Of + tm * 16 * 68 + (tn0 + 0) * 16, acc[0], 68, wmma::mem_row_major);
    wmma::store_matrix_sync(Of + tm * 16 * 68 + (tn0 + 1) * 16, acc[1], 68, wmma::mem_row_major);
    __syncthreads();
    for (int i = t; i < 4096; i += 256) {
        int s = i >> 6, oc = i & 63;
        int cell = sCell[s];
        if (cell >= 0) {
            float v = fmaxf(Of[s * 68 + oc] + beta[oc0 + oc], 0.0f);
            if (SPLIT_OUT) {
                __nv_bfloat16 h = __float2bfloat16(v);
                ofh[(size_t)cell * OCALL + oc0 + oc] = h;
                ofl[(size_t)cell * OCALL + oc0 + oc] = __float2bfloat16(v - __bfloat162float(h));
            } else {
                outF[(size_t)cell * OCALL + oc0 + oc] = v;
            }
        }
    }
}
template<int IC> constexpr int wsmem() {
    int a = (2 * 64 * (IC + 8) + 2 * IC * 72) * 2;
    return a > 17408 ? a : 17408;
}

// ---------------- BEV im2col (bf16 split, [p][r] layout) --------------------
__global__ void im2col1_bf(__nv_bfloat16* __restrict__ ch_, __nv_bfloat16* __restrict__ cl_) {
    int idx = blockIdx.x * blockDim.x + threadIdx.x;
    if (idx >= P2D * K1D) return;
    int p = idx / K1D;
    int r = idx % K1D;
    int k = r / 1280, chn = r % 1280;
    int ky = k / 3, kx = k % 3;
    int y = p / 25, x = p % 25;
    int sy = y + ky - 1, sx = x + kx - 1;
    float v = 0.0f;
    if (sy >= 0 && sy < 25 && sx >= 0 && sx < 25) {
        int z = chn >> 8, c = chn & 255;
        int site = z * P2D + sy * 25 + sx;
        if (g_m2[site]) v = g_feat4[(size_t)site * 256 + c];
    }
    __nv_bfloat16 h = __float2bfloat16(v);
    ch_[idx] = h;
    cl_[idx] = __float2bfloat16(v - __bfloat162float(h));
}

__global__ void im2col2_bf(__nv_bfloat16* __restrict__ ch_, __nv_bfloat16* __restrict__ cl_) {
    int idx = blockIdx.x * blockDim.x + threadIdx.x;
    if (idx >= P2D * K2D) return;
    int p = idx / K2D;
    int r = idx % K2D;
    int k = r / 512, chn = r % 512;
    int ky = k / 3, kx = k % 3;
    int y = p / 25, x = p % 25;
    int sy = y + ky - 1, sx = x + kx - 1;
    __nv_bfloat16 h = __float2bfloat16(0.f), l = h;
    if (sy >= 0 && sy < 25 && sx >= 0 && sx < 25) {
        int src = chn * P2D + sy * 25 + sx;
        h = g_bev1h[src];
        l = g_bev1l[src];
    }
    ch_[idx] = h;
    cl_[idx] = l;
}

// ---------------- BEV GEMM: wmma bf16 3-pass split, split-K, cp.async -------
template<int OCALL, int K, int SPLIT>
__global__ void __launch_bounds__(256) gemm_wmma(
    const __nv_bfloat16* __restrict__ ah_, const __nv_bfloat16* __restrict__ al_,
    const __nv_bfloat16* __restrict__ bh_, const __nv_bfloat16* __restrict__ bl_)
{
    constexpr int LD = 72;
    extern __shared__ __align__(16) char sm[];
    __nv_bfloat16* Ah = reinterpret_cast<__nv_bfloat16*>(sm);
    __nv_bfloat16* Al = Ah + 64 * LD;
    __nv_bfloat16* Bh = Al + 64 * LD;
    __nv_bfloat16* Bl = Bh + 64 * LD;
    const int t = threadIdx.x, w = t >> 5;
    const int p0 = blockIdx.x * 64, oc0 = blockIdx.y * 64;
    constexpr int KCper = K / SPLIT;
    const int kbeg = blockIdx.z * KCper;
    const uint32_t aAh = s2u(Ah), aAl = s2u(Al), aBh = s2u(Bh), aBl = s2u(Bl);
    wmma::fragment<wmma::accumulator, 16, 16, 16, float> acc[2];
    wmma::fill_fragment(acc[0], 0.0f);
    wmma::fill_fragment(acc[1], 0.0f);
    const int tm = w >> 1;
    const int tn0 = (w & 1) * 2;
    for (int k0 = kbeg; k0 < kbeg + KCper; k0 += 64) {
        for (int i = t; i < 512; i += 256) {
            int row = i >> 3, c = i & 7;
            int p = p0 + row;
            uint32_t so = (uint32_t)(row * LD + c * 8) * 2;
            unsigned ss = (p < P2D) ? 16u : 0u;
            const __nv_bfloat16* gh = (p < P2D) ? (ah_ + (size_t)p * K + k0 + c * 8) : ah_;
            const __nv_bfloat16* gl = (p < P2D) ? (al_ + (size_t)p * K + k0 + c * 8) : al_;
            cpa16(aAh + so, gh, ss);
            cpa16(aAl + so, gl, ss);
            cpa16f(aBh + so, bh_ + (size_t)(k0 + row) * OCALL + oc0 + c * 8);
            cpa16f(aBl + so, bl_ + (size_t)(k0 + row) * OCALL + oc0 + c * 8);
        }
        cpa_wait();
        __syncthreads();
#pragma unroll
        for (int kk = 0; kk < 4; kk++) {
            wmma::fragment<wmma::matrix_a, 16, 16, 16, __nv_bfloat16, wmma::row_major> aH, aL;
            wmma::load_matrix_sync(aH, Ah + tm * 16 * LD + kk * 16, LD);
            wmma::load_matrix_sync(aL, Al + tm * 16 * LD + kk * 16, LD);
#pragma unroll
            for (int e = 0; e < 2; e++) {
                wmma::fragment<wmma::matrix_b, 16, 16, 16, __nv_bfloat16, wmma::row_major> bH, bL;
                wmma::load_matrix_sync(bH, Bh + kk * 16 * LD + (tn0 + e) * 16, LD);
                wmma::load_matrix_sync(bL, Bl + kk * 16 * LD + (tn0 + e) * 16, LD);
                wmma::mma_sync(acc[e], aH, bH, acc[e]);
                wmma::mma_sync(acc[e], aH, bL, acc[e]);
                wmma::mma_sync(acc[e], aL, bH, acc[e]);
            }
        }
        __syncthreads();
    }
    float* Of = reinterpret_cast<float*>(sm);
    wmma::store_matrix_sync(Of + tm * 16 * 68 + (tn0 + 0) * 16, acc[0], 68, wmma::mem_row_major);
    wmma::store_matrix_sync(Of + tm * 16 * 68 + (tn0 + 1) * 16, acc[1], 68, wmma::mem_row_major);
    __syncthreads();
    float* gp = g_part + (size_t)blockIdx.z * OCALL * P2D;
    for (int i = t; i < 4096; i += 256) {
        int row = i >> 6, oc = i & 63;
        int p = p0 + row;
        if (p < P2D) gp[(size_t)(oc0 + oc) * P2D + p] = Of[row * 68 + oc];
    }
}
static constexpr int GEMM_SMEM = 4 * 64 * 72 * 2;   // 36864

// combine gemm1 partials -> bias+relu -> bf16 split bev1
__global__ void combine1_bf(const float* __restrict__ bias) {
    int idx = blockIdx.x * blockDim.x + threadIdx.x;
    if (idx >= 512 * P2D) return;
    int oc = idx / P2D;
    float s = bias[oc];
#pragma unroll
    for (int z = 0; z < 4; z++) s += g_part[(size_t)z * 512 * P2D + idx];
    float v = fmaxf(s, 0.0f);
    __nv_bfloat16 h = __float2bfloat16(v);
    g_bev1h[idx] = h;
    g_bev1l[idx] = __float2bfloat16(v - __bfloat162float(h));
}

// final: combine2 + re-zero all state for next call
static constexpr int COMB2_BLOCKS = (256 * P2D + 255) / 256;
static constexpr int ZC0 = NVOX;
static constexpr int ZC1 = NVOX / 4;
static constexpr int ZC2 = N1 / 4;
static constexpr int ZC3 = N2;
static constexpr int ZTOT = ZC0 + ZC1 + ZC2 + ZC3 + 3;
static constexpr int ZBLK = (ZTOT + 255) / 256;

__global__ void final_combine_zero(const float* __restrict__ bias, float* __restrict__ out) {
    if (blockIdx.x < COMB2_BLOCKS) {
        int idx = blockIdx.x * 256 + threadIdx.x;
        if (idx >= 256 * P2D) return;
        int oc = idx / P2D;
        float s = bias[oc];
#pragma unroll
        for (int z = 0; z < 4; z++) s += g_part[(size_t)z * 256 * P2D + idx];
        out[idx] = fmaxf(s, 0.0f);
        return;
    }
    int idx = (blockIdx.x - COMB2_BLOCKS) * 256 + threadIdx.x;
    if (idx < ZC0) { g_count[idx] = 0; return; } idx -= ZC0;
    if (idx < ZC1) { reinterpret_cast<int*>(g_m0)[idx] = 0; return; } idx -= ZC1;
    if (idx < ZC2) { reinterpret_cast<int*>(g_m1)[idx] = 0; return; } idx -= ZC2;
    if (idx < ZC3) { g_m2[idx] = 0; return; } idx -= ZC3;
    if (idx < 3) { g_cntArr[idx] = 0; return; }
}

// ---------------- host ----------------
static inline void* sym(const void* s) { void* p = nullptr; cudaGetSymbolAddress(&p, s); return p; }

extern "C" void kernel_launch(void* const* d_in, const int* in_sizes, int n_in,
                              void* d_out, int out_size) {
    const float* points = (const float*)d_in[0];
    const float *vfe1_w = (const float*)d_in[1], *vfe1_b = (const float*)d_in[2],
                *vfe1_g = (const float*)d_in[3], *vfe1_be = (const float*)d_in[4];
    const float *vfe2_w = (const float*)d_in[5], *vfe2_b = (const float*)d_in[6],
                *vfe2_g = (const float*)d_in[7], *vfe2_be = (const float*)d_in[8];
    const float *sp1_w = (const float*)d_in[9],  *sp1_g = (const float*)d_in[10], *sp1_be = (const float*)d_in[11];
    const float *sp2_w = (const float*)d_in[12], *sp2_g = (const float*)d_in[13], *sp2_be = (const float*)d_in[14];
    const float *sp3_w = (const float*)d_in[15], *sp3_g = (const float*)d_in[16], *sp3_be = (const float*)d_in[17];
    const float *sp4_w = (const float*)d_in[18], *sp4_g = (const float*)d_in[19], *sp4_be = (const float*)d_in[20];
    const float *bev1_w = (const float*)d_in[21], *bev1_b = (const float*)d_in[22],
                *bev1_g = (const float*)d_in[23], *bev1_be = (const float*)d_in[24];
    const float *bev2_w = (const float*)d_in[25], *bev2_b = (const float*)d_in[26],
                *bev2_g = (const float*)d_in[27], *bev2_be = (const float*)d_in[28];

    int Npts = in_sizes[0] / 5;

    float* bb1 = (float*)sym(g_bb1);  float* bb2 = (float*)sym(g_bb2);
    unsigned char* m0 = (unsigned char*)sym(g_m0);
    unsigned char* m1 = (unsigned char*)sym(g_m1);
    int* l0c = (int*)sym(g_list0cell);
    int* l1 = (int*)sym(g_list1); int* l2 = (int*)sym(g_list2);
    const __nv_bfloat16* f0h = (const __nv_bfloat16*)sym(g_f0h);
    const __nv_bfloat16* f0l = (const __nv_bfloat16*)sym(g_f0l);
    __nv_bfloat16* f1h = (__nv_bfloat16*)sym(g_f1h);
    __nv_bfloat16* f1l = (__nv_bfloat16*)sym(g_f1l);
    __nv_bfloat16* f2h = (__nv_bfloat16*)sym(g_f2h);
    __nv_bfloat16* f2l = (__nv_bfloat16*)sym(g_f2l);
    __nv_bfloat16* f3h = (__nv_bfloat16*)sym(g_f3h);
    __nv_bfloat16* f3l = (__nv_bfloat16*)sym(g_f3l);
    const __nv_bfloat16* w1h = (const __nv_bfloat16*)sym(g_w1bfh);
    const __nv_bfloat16* w1l = (const __nv_bfloat16*)sym(g_w1bfl);
    const __nv_bfloat16* w2h = (const __nv_bfloat16*)sym(g_w2bfh);
    const __nv_bfloat16* w2l = (const __nv_bfloat16*)sym(g_w2bfl);
    const __nv_bfloat16* w3h = (const __nv_bfloat16*)sym(g_w3bfh);
    const __nv_bfloat16* w3l = (const __nv_bfloat16*)sym(g_w3bfl);
    const __nv_bfloat16* w4h = (const __nv_bfloat16*)sym(g_w4bfh);
    const __nv_bfloat16* w4l = (const __nv_bfloat16*)sym(g_w4bfl);
    __nv_bfloat16* c1h = (__nv_bfloat16*)sym(g_col1h);
    __nv_bfloat16* c1l = (__nv_bfloat16*)sym(g_col1l);
    __nv_bfloat16* c2h = (__nv_bfloat16*)sym(g_col2h);
    __nv_bfloat16* c2l = (__nv_bfloat16*)sym(g_col2l);
    const __nv_bfloat16* wb1h = (const __nv_bfloat16*)sym(g_wb1h);
    const __nv_bfloat16* wb1l = (const __nv_bfloat16*)sym(g_wb1l);
    const __nv_bfloat16* wb2h = (const __nv_bfloat16*)sym(g_wb2h);
    const __nv_bfloat16* wb2l = (const __nv_bfloat16*)sym(g_wb2l);

    auto k1 = spconv_wmmaG<128, 64, 1, 20, 100, 100, 20, 100, 100, true>;
    auto k2 = spconv_wmmaG<64, 128, 2, 20, 100, 100, 10, 50, 50, true>;
    auto k3 = spconv_wmmaG<128, 128, 1, 10, 50, 50, 10, 50, 50, true>;
    auto k4 = spconv_wmmaG<128, 256, 2, 10, 50, 50, 5, 25, 25, false>;
    cudaFuncSetAttribute(k1, cudaFuncAttributeMaxDynamicSharedMemorySize, wsmem<128>());
    cudaFuncSetAttribute(k2, cudaFuncAttributeMaxDynamicSharedMemorySize, wsmem<64>());
    cudaFuncSetAttribute(k3, cudaFuncAttributeMaxDynamicSharedMemorySize, wsmem<128>());
    cudaFuncSetAttribute(k4, cudaFuncAttributeMaxDynamicSharedMemorySize, wsmem<128>());

    // 0: scatter + weight prep
    scatter_prep<<<SCAT_BLOCKS + PREP_BLOCKS, 256>>>(
        points, Npts,
        sp1_w, sp1_g, sp2_w, sp2_g, sp3_w, sp3_g, sp4_w, sp4_g,
        bev1_w, bev1_g, bev2_w, bev2_g, bev1_b, bev1_be, bev2_b, bev2_be,
        vfe1_w, vfe1_b, vfe1_g, vfe1_be, vfe2_w, vfe2_b, vfe2_g, vfe2_be);
    // 1: scan
    scan_opt<<<1, 1024>>>();
    // 2: VFE
    vfe_warp<<<(MAXV + 7) / 8, 256>>>();
    // 3: sp1 wmma (profiled launch)
    {
        dim3 g((MAXV + 63) / 64, 1);
        k1<<<g, 256, wsmem<128>()>>>(f0h, f0l, m0, w1h, w1l, sp1_be, l0c, 0,
                                     f1h, f1l, nullptr);
    }
    // 4:
    pool1<<<(N1 + 255) / 256, 256>>>();
    // 5: sp2 wmma
    {
        dim3 g((N1 + 63) / 64, 2);
        k2<<<g, 256, wsmem<64>()>>>(f1h, f1l, m0, w2h, w2l, sp2_be, l1, 1,
                                    f2h, f2l, nullptr);
    }
    // 6: sp3 wmma
    {
        dim3 g((N1 + 63) / 64, 2);
        k3<<<g, 256, wsmem<128>()>>>(f2h, f2l, m1, w3h, w3l, sp3_be, l1, 1,
                                     f3h, f3l, nullptr);
    }
    // 7:
    pool2<<<(N2 + 255) / 256, 256>>>();
    // 8: sp4 wmma (float out)
    {
        dim3 g((N2 + 63) / 64, 4);
        k4<<<g, 256, wsmem<128>()>>>(f3h, f3l, m1, w4h, w4l, sp4_be, l2, 2,
                                     nullptr, nullptr, (float*)sym(g_feat4));
    }
    // 9: im2col1 (bf16 split)
    im2col1_bf<<<(P2D * K1D + 255) / 256, 256>>>(c1h, c1l);
    // 10: gemm1 wmma
    {
        dim3 g((P2D + 63) / 64, 512 / 64, 4);
        gemm_wmma<512, K1D, 4><<<g, 256, GEMM_SMEM>>>(c1h, c1l, wb1h, wb1l);
    }
    // 11: combine1 -> bf16 split
    combine1_bf<<<(512 * P2D + 255) / 256, 256>>>(bb1);
    // 12: im2col2 (bf16 copy)
    im2col2_bf<<<(P2D * K2D + 255) / 256, 256>>>(c2h, c2l);
    // 13: gemm2 wmma
    {
        dim3 g((P2D + 63) / 64, 256 / 64, 4);
        gemm_wmma<256, K2D, 4><<<g, 256, GEMM_SMEM>>>(c2h, c2l, wb2h, wb2l);
    }
    // 14: combine2 + re-zero state
    final_combine_zero<<<COMB2_BLOCKS + ZBLK, 256>>>(bb2, (float*)d_out);
}